// round 5
// baseline (speedup 1.0000x reference)
#include <cuda_runtime.h>
#include <cuda_fp16.h>
#include <cstdint>
#include <math.h>

#define BSZ   256
#define NLEAF 64
#define SZ    512
#define D2    1024
#define GN    2560
#define RMAX  64

#define BM    64
#define BN    80
#define NTH   512
#define NCTA  128

// smem layout (bytes)
#define ASTG  9216                  // one A stage: 64 rows x 144B (128B data + 16 pad)
#define NST   3
#define AOFF  0
#define BOFF  (NST * ASTG)          // 27648
#define BROW  2064                  // B row stride: 1024 halfs (2048B) + 16 pad
#define BBYTES (80 * BROW)          // 165120
#define CTRL  (BOFF + BBYTES)       // 192768
#define OLH   (CTRL)
#define ORH   (CTRL + 512)
#define OLC   (CTRL + 1024)
#define ORC   (CTRL + 1536)
#define OVAL  (CTRL + 2048)
#define SMEM_TOTAL (CTRL + 2304)    // 195072

// ---------------- device scratch ----------------
__device__ __half   g_h[BSZ][129][SZ];      // 0..63 leaves, 64..127 results, 128 zero
__device__ float    g_c[BSZ][RMAX + 1][SZ];
__device__ float    g_hf[BSZ][RMAX][SZ];
__device__ __half   g_Wt[(size_t)GN * D2];  // [dc][k] gate-interleaved, transposed
__device__ float    g_bias[GN];
__device__ int      g_lop[BSZ * RMAX];
__device__ int      g_rop[BSZ * RMAX];
__device__ int      g_nred[BSZ];
__device__ int      g_top[BSZ];
__device__ unsigned g_bar4[4];

__device__ __forceinline__ float sigm(float x) { return 1.0f / (1.0f + expf(-x)); }

// ---------------- PTX helpers ----------------
__device__ __forceinline__ void cp16(uint32_t sdst, const void* gsrc) {
    asm volatile("cp.async.cg.shared.global [%0], [%1], 16;\n" :: "r"(sdst), "l"(gsrc));
}
__device__ __forceinline__ void cp_commit() { asm volatile("cp.async.commit_group;\n" ::); }
template <int N> __device__ __forceinline__ void cp_wait() {
    asm volatile("cp.async.wait_group %0;\n" :: "n"(N));
}
__device__ __forceinline__ void ldsm4(uint32_t* r, uint32_t addr) {
    asm volatile("ldmatrix.sync.aligned.m8n8.x4.shared.b16 {%0,%1,%2,%3},[%4];\n"
                 : "=r"(r[0]), "=r"(r[1]), "=r"(r[2]), "=r"(r[3]) : "r"(addr));
}
__device__ __forceinline__ void ldsm2(uint32_t& r0, uint32_t& r1, uint32_t addr) {
    asm volatile("ldmatrix.sync.aligned.m8n8.x2.shared.b16 {%0,%1},[%2];\n"
                 : "=r"(r0), "=r"(r1) : "r"(addr));
}
__device__ __forceinline__ void mma16816(float* c, const uint32_t* a, uint32_t b0, uint32_t b1) {
    asm volatile(
        "mma.sync.aligned.m16n8k16.row.col.f32.f16.f16.f32 "
        "{%0,%1,%2,%3},{%4,%5,%6,%7},{%8,%9},{%0,%1,%2,%3};\n"
        : "+f"(c[0]), "+f"(c[1]), "+f"(c[2]), "+f"(c[3])
        : "r"(a[0]), "r"(a[1]), "r"(a[2]), "r"(a[3]), "r"(b0), "r"(b1));
}

// ---------------- setup: leaves->fp16 (vec4) + zero slots ----------------
__global__ void setup_kernel(const float* __restrict__ buffers) {
    int bid = blockIdx.x, tid = threadIdx.x;
    if (bid < 8192) {
        int i4 = (bid * 256 + tid) * 4;
        int b = i4 >> 15, rem = i4 & 32767;
        int r = rem >> 9, j = rem & 511;
        float4 v = *(const float4*)(buffers + ((size_t)b << 16) + ((size_t)r << 10) + j);
        __half2 h0 = __floats2half2_rn(v.x, v.y);
        __half2 h1 = __floats2half2_rn(v.z, v.w);
        uint2 pk = make_uint2(*(uint32_t*)&h0, *(uint32_t*)&h1);
        *(uint2*)&g_h[b][r][j] = pk;
    } else {
        int i = (bid - 8192) * 256 + tid;
        int b = i >> 9, j = i & 511;
        g_h[b][128][j] = __half(0.0f);
        g_c[b][RMAX][j] = 0.0f;
    }
}

// ---------------- weights: fp32 -> fp16, gate-interleave + transpose ----------------
__global__ void convert_w_kernel(const float* __restrict__ Wl,
                                 const float* __restrict__ Wr,
                                 const float* __restrict__ bl) {
    __shared__ float tile[40][33];
    int tid = threadIdx.x;
    int dcb = blockIdx.x >> 5;
    int kb  = blockIdx.x & 31;
    int dc0 = dcb * 40, k0 = kb * 32, j0 = dcb * 8;
    for (int e = tid; e < 1280; e += 256) {
        int jj = e & 7, g = (e >> 3) % 5, k = e / 40;
        int sc = g * SZ + j0 + jj;
        int kk = k0 + k;
        float v = (kk < SZ) ? Wl[(size_t)kk * GN + sc] : Wr[(size_t)(kk - SZ) * GN + sc];
        tile[5 * jj + g][k] = v;
    }
    __syncthreads();
    for (int e = tid; e < 1280; e += 256) {
        int kk = e & 31, dcl = e >> 5;
        g_Wt[((size_t)(dc0 + dcl) << 10) + k0 + kk] = __float2half(tile[dcl][kk]);
    }
    if (kb == 0 && tid < 40) {
        int dc = dc0 + tid, j = dc / 5, g = dc % 5;
        g_bias[dc] = bl[g * SZ + j];
    }
}

// ---------------- schedule: smem stacks + barrier reset ----------------
__global__ void schedule_kernel(const int* __restrict__ trans, int T) {
    __shared__ int st[136][33];
    int lt = threadIdx.x;
    int b = blockIdx.x * 32 + lt;
    if (blockIdx.x == 0 && lt < 4) g_bar4[lt] = 0;
    for (int i = 0; i < 136; i++) st[i][lt] = 128;
    int ptr = 0, bptr = 0, nr = 0;
    for (int t = 0; t < T; t++) {
        int tr = trans[b * T + t];
        if (tr == 0) {                                   // SHIFT
            int n = (bptr < NLEAF - 1) ? bptr : (NLEAF - 1);
            int wp = ptr; if (wp < 0) wp = 0; if (wp > 130) wp = 130;
            st[wp][lt] = n;
            ptr++; bptr++;
        } else if (tr == 1) {                            // REDUCE
            int lp = ptr - 2; if (lp < 0) lp = 0;
            int rp = ptr - 1; if (rp < 0) rp = 0;
            if (nr < RMAX) {
                g_lop[(b << 6) + nr] = st[lp][lt];
                g_rop[(b << 6) + nr] = st[rp][lt];
                st[lp][lt] = 64 + nr;
                nr++;
            }
            ptr--;
        }
    }
    g_nred[b] = nr;
    int tp = ptr - 1; if (tp < 0) tp = 0; if (tp > 130) tp = 130;
    g_top[b] = st[tp][lt];
}

// ---------------- persistent SPINN kernel ----------------
// grid (32, 4) = 128 CTAs, 512 threads = 16 warps: kg(4 k-split) x wm(2) x wn(2)
__global__ __launch_bounds__(NTH, 1) void spinn_kernel(const float* __restrict__ buffers, int RL) {
    extern __shared__ __align__(16) char smem[];
    uint32_t sb = (uint32_t)__cvta_generic_to_shared(smem);
    const __half** s_lh = (const __half**)(smem + OLH);
    const __half** s_rh = (const __half**)(smem + ORH);
    const float**  s_lc = (const float**)(smem + OLC);
    const float**  s_rc = (const float**)(smem + ORC);
    int* s_valid = (int*)(smem + OVAL);

    int tid = threadIdx.x, warp = tid >> 5, lane = tid & 31;
    int kg = warp >> 2;                 // 0..3 K-split group
    int wm = (warp >> 1) & 1;           // m half
    int wn = warp & 1;                  // n half
    int wr = wm * 32, wc = wn * 40;
    int row0 = blockIdx.y * BM, col0 = blockIdx.x * BN;
    int by = blockIdx.y;

    // ---- load resident B tile: 80 rows x 2048B (padded stride 2064) ----
    #pragma unroll
    for (int i = 0; i < 20; i++) {
        int idx = tid + i * NTH;                 // 0..10239
        int r = idx >> 7, c = idx & 127;
        cp16(sb + BOFF + (uint32_t)(r * BROW + c * 16),
             (const char*)g_Wt + ((size_t)(col0 + r) << 11) + c * 16);
    }
    cp_commit(); cp_wait<0>(); __syncthreads();

    // epilogue constants (thread owns hidden unit jl of this CTA, rows tid>>4 and +32)
    int jl = tid & 15;
    int jg0 = blockIdx.x * 16 + jl;
    float bias[5];
    #pragma unroll
    for (int g = 0; g < 5; g++) bias[g] = g_bias[col0 + jl * 5 + g];

    // A producer: 512 threads x 16B = one K64 stage (64 rows x 128B)
    int ar = tid >> 3, ach = tid & 7;
    uint32_t adst0 = sb + AOFF + (uint32_t)(ar * 144 + ach * 16);

    // fragment lane addresses
    uint32_t aln = (uint32_t)((wr + (lane & 7) + ((lane >> 3) & 1) * 8) * 144
                              + ((lane >> 4) & 1) * 16 + kg * 32);
    uint32_t bln = sb + BOFF + (uint32_t)((wc + (lane & 7)) * BROW
                                          + ((lane >> 3) & 1) * 16 + kg * 32);
    int gp = lane >> 2, t4 = lane & 3;

    float (*Gs)[BN + 1] = (float (*)[BN + 1])smem;    // reuses A stages after drain

    for (int k = 0; k < RL; k++) {
        int v = 0;
        if (tid < BM) {
            int b = row0 + tid;
            int lop = g_lop[(b << 6) + k];
            int rop = g_rop[(b << 6) + k];
            s_lh[tid] = &g_h[b][lop][0];
            s_rh[tid] = &g_h[b][rop][0];
            s_lc[tid] = (lop < 64)  ? (buffers + ((size_t)b << 16) + ((size_t)lop << 10) + SZ)
                      : (lop < 128) ? &g_c[b][lop - 64][0] : &g_c[b][RMAX][0];
            s_rc[tid] = (rop < 64)  ? (buffers + ((size_t)b << 16) + ((size_t)rop << 10) + SZ)
                      : (rop < 128) ? &g_c[b][rop - 64][0] : &g_c[b][RMAX][0];
            v = s_valid[tid] = (k < g_nred[b]) ? 1 : 0;
        }
        if (__syncthreads_or(v)) {
            const __half* lh = s_lh[ar];
            const __half* rh = s_rh[ar];

            auto issue = [&](int s) {
                int k0 = s * 64;
                const __half* src = ((k0 < SZ) ? lh : rh) + (k0 & 511) + ach * 8;
                cp16(adst0 + (uint32_t)(s % NST) * ASTG, src);
            };

            float acc[2][5][4];
            #pragma unroll
            for (int su = 0; su < 2; su++)
                #pragma unroll
                for (int f = 0; f < 5; f++)
                    #pragma unroll
                    for (int q = 0; q < 4; q++) acc[su][f][q] = 0.0f;

            auto compute = [&](int s) {
                uint32_t abase = sb + (uint32_t)(s % NST) * ASTG + aln;
                uint32_t bbase = bln + (uint32_t)(s * 128);
                uint32_t a0[4], a1[4];
                ldsm4(a0, abase);
                ldsm4(a1, abase + 16 * 144);
                #pragma unroll
                for (int f = 0; f < 5; f++) {
                    uint32_t b0, b1;
                    ldsm2(b0, b1, bbase + (uint32_t)(f * 8 * BROW));
                    mma16816(acc[0][f], a0, b0, b1);
                    mma16816(acc[1][f], a1, b0, b1);
                }
            };

            issue(0); cp_commit();
            issue(1); cp_commit();
            for (int s = 0; s < 15; s++) {
                cp_wait<1>();
                __syncthreads();
                compute(s);
                if (s + 2 < 16) issue(s + 2);
                cp_commit();
            }
            cp_wait<0>();
            __syncthreads();
            compute(15);
            __syncthreads();          // all stage reads done before Gs overwrites

            // ---- K-split reduction into Gs ----
            #pragma unroll
            for (int pass = 3; pass >= 0; pass--) {
                if (kg == pass) {
                    #pragma unroll
                    for (int su = 0; su < 2; su++)
                        #pragma unroll
                        for (int f = 0; f < 5; f++) {
                            int rr = wr + su * 16 + gp, cc = wc + f * 8 + t4 * 2;
                            if (pass == 3) {
                                Gs[rr][cc]         = acc[su][f][0];
                                Gs[rr][cc + 1]     = acc[su][f][1];
                                Gs[rr + 8][cc]     = acc[su][f][2];
                                Gs[rr + 8][cc + 1] = acc[su][f][3];
                            } else {
                                Gs[rr][cc]         += acc[su][f][0];
                                Gs[rr][cc + 1]     += acc[su][f][1];
                                Gs[rr + 8][cc]     += acc[su][f][2];
                                Gs[rr + 8][cc + 1] += acc[su][f][3];
                            }
                        }
                }
                __syncthreads();
            }

            // ---- LSTM epilogue: 2 items per thread (rows tid>>4, +32), unit jl ----
            #pragma unroll
            for (int i = 0; i < 2; i++) {
                int r = (tid >> 4) + i * 32;
                if (s_valid[r]) {
                    int b  = row0 + r;
                    int cb = jl * 5;
                    float a  = Gs[r][cb + 0] + bias[0];
                    float ii = Gs[r][cb + 1] + bias[1];
                    float f1 = Gs[r][cb + 2] + bias[2];
                    float f2 = Gs[r][cb + 3] + bias[3];
                    float o  = Gs[r][cb + 4] + bias[4];
                    float lc = s_lc[r][jg0];
                    float rc = s_rc[r][jg0];
                    float cc = tanhf(a) * sigm(ii) + sigm(f1) * lc + sigm(f2) * rc;
                    float hh = sigm(o) * tanhf(cc);
                    g_h[b][64 + k][jg0] = __float2half(hh);
                    g_hf[b][k][jg0]     = hh;
                    g_c[b][k][jg0]      = cc;
                }
            }
        }

        // ---- row-group barrier (32 CTAs sharing this row block) ----
        __syncthreads();
        __threadfence();
        if (tid == 0) {
            atomicAdd(&g_bar4[by], 1u);
            unsigned tgt = (unsigned)(32 * (k + 1));
            while (*((volatile unsigned*)&g_bar4[by]) < tgt) { }
        }
        __syncthreads();
        __threadfence();
    }
}

// ---------------- final gather ----------------
__global__ void final_kernel(const float* __restrict__ buffers, float* __restrict__ out) {
    int i = blockIdx.x * blockDim.x + threadIdx.x;
    if (i >= BSZ * SZ) return;
    int b = i / SZ, j = i % SZ;
    int op = g_top[b];
    float v;
    if (op < 64)       v = buffers[((size_t)b << 16) + ((size_t)op << 10) + j];
    else if (op < 128) v = g_hf[b][op - 64][j];
    else               v = 0.0f;
    out[i] = v;
}

// ---------------- launch ----------------
extern "C" void kernel_launch(void* const* d_in, const int* in_sizes, int n_in,
                              void* d_out, int out_size) {
    const float* buffers = (const float*)d_in[0];
    const int*   trans   = (const int*)d_in[1];
    const float* Wl      = (const float*)d_in[2];
    const float* Wr      = (const float*)d_in[3];
    const float* bl      = (const float*)d_in[4];
    float*       out     = (float*)d_out;

    int T  = in_sizes[1] / BSZ;
    int RL = (T + 1) / 2;
    if (RL > RMAX) RL = RMAX;

    static int attr_done = 0;
    if (!attr_done) {
        cudaFuncSetAttribute(spinn_kernel, cudaFuncAttributeMaxDynamicSharedMemorySize,
                             SMEM_TOTAL);
        attr_done = 1;
    }

    schedule_kernel<<<8, 32>>>(trans, T);
    setup_kernel<<<8192 + 512, 256>>>(buffers);
    convert_w_kernel<<<2048, 256>>>(Wl, Wr, bl);

    dim3 grid(GN / BN, BSZ / BM);   // (32, 4) = 128 CTAs
    spinn_kernel<<<grid, NTH, SMEM_TOTAL>>>(buffers, RL);

    final_kernel<<<(BSZ * SZ + 255) / 256, 256>>>(buffers, out);
}

// round 6
// speedup vs baseline: 1.1466x; 1.1466x over previous
#include <cuda_runtime.h>
#include <cuda_fp16.h>
#include <cstdint>
#include <math.h>

#define BSZ   256
#define NLEAF 64
#define SZ    512
#define D2    1024
#define GN    2560
#define RMAX  64

#define BM    64
#define BN    80
#define NTH   512

// spinn smem layout (bytes): A(=Gs) | B1(Wl slice) | B2(Wr slice) | ctrl
#define AOFF   0
#define B1OFF  65536
#define B2OFF  147456
#define CTRL   229376
#define OLH    (CTRL)
#define ORH    (CTRL + 512)
#define OLC    (CTRL + 1024)
#define ORC    (CTRL + 1536)
#define OROP   (CTRL + 2048)
#define OVAL   (CTRL + 2304)
#define SMEM_TOTAL (CTRL + 2560)     // 231936 <= 232448 opt-in max

// pr_kernel smem: 3 A stages (16KB) then B (160KB)
#define PR_BOFF 49152
#define PR_SMEM (PR_BOFF + 163840)   // 212992

// ---------------- device scratch ----------------
__device__ __half   g_h[BSZ][129][SZ];      // 0..63 leaves, 64..127 results, 128 zero
__device__ float    g_c[BSZ][RMAX + 1][SZ];
__device__ float    g_hf[BSZ][RMAX][SZ];
__device__ __half   g_Wt[(size_t)GN * D2];  // [dc][k] gate-interleaved, transposed
__device__ float    g_bias[GN];
__device__ float    g_PR[(size_t)BSZ * NLEAF * GN]; // leaf @ Wr, gate-interleaved cols
__device__ int      g_lop[BSZ * RMAX];
__device__ int      g_rop[BSZ * RMAX];
__device__ int      g_nred[BSZ];
__device__ int      g_top[BSZ];
__device__ int      g_badR[RMAX];           // zero-init; 1 if some rop is a reduce result
__device__ unsigned g_bar4[4];

__device__ __forceinline__ float sigm(float x) { return 1.0f / (1.0f + expf(-x)); }

// ---------------- PTX helpers ----------------
__device__ __forceinline__ void cp16(uint32_t sdst, const void* gsrc) {
    asm volatile("cp.async.cg.shared.global [%0], [%1], 16;\n" :: "r"(sdst), "l"(gsrc));
}
__device__ __forceinline__ void cp_commit() { asm volatile("cp.async.commit_group;\n" ::); }
template <int N> __device__ __forceinline__ void cp_wait() {
    asm volatile("cp.async.wait_group %0;\n" :: "n"(N));
}
__device__ __forceinline__ void ldsm4(uint32_t* r, uint32_t addr) {
    asm volatile("ldmatrix.sync.aligned.m8n8.x4.shared.b16 {%0,%1,%2,%3},[%4];\n"
                 : "=r"(r[0]), "=r"(r[1]), "=r"(r[2]), "=r"(r[3]) : "r"(addr));
}
__device__ __forceinline__ void ldsm2(uint32_t& r0, uint32_t& r1, uint32_t addr) {
    asm volatile("ldmatrix.sync.aligned.m8n8.x2.shared.b16 {%0,%1},[%2];\n"
                 : "=r"(r0), "=r"(r1) : "r"(addr));
}
__device__ __forceinline__ void mma16816(float* c, const uint32_t* a, uint32_t b0, uint32_t b1) {
    asm volatile(
        "mma.sync.aligned.m16n8k16.row.col.f32.f16.f16.f32 "
        "{%0,%1,%2,%3},{%4,%5,%6,%7},{%8,%9},{%0,%1,%2,%3};\n"
        : "+f"(c[0]), "+f"(c[1]), "+f"(c[2]), "+f"(c[3])
        : "r"(a[0]), "r"(a[1]), "r"(a[2]), "r"(a[3]), "r"(b0), "r"(b1));
}

// ---------------- setup: leaves->fp16 (vec4) + zero slots ----------------
__global__ void setup_kernel(const float* __restrict__ buffers) {
    int bid = blockIdx.x, tid = threadIdx.x;
    if (bid < 8192) {
        int i4 = (bid * 256 + tid) * 4;
        int b = i4 >> 15, rem = i4 & 32767;
        int r = rem >> 9, j = rem & 511;
        float4 v = *(const float4*)(buffers + ((size_t)b << 16) + ((size_t)r << 10) + j);
        __half2 h0 = __floats2half2_rn(v.x, v.y);
        __half2 h1 = __floats2half2_rn(v.z, v.w);
        *(uint2*)&g_h[b][r][j] = make_uint2(*(uint32_t*)&h0, *(uint32_t*)&h1);
    } else {
        int i = (bid - 8192) * 256 + tid;
        int b = i >> 9, j = i & 511;
        g_h[b][128][j] = __half(0.0f);
        g_c[b][RMAX][j] = 0.0f;
    }
}

// ---------------- weights: fp32 -> fp16, gate-interleave + transpose ----------------
__global__ void convert_w_kernel(const float* __restrict__ Wl,
                                 const float* __restrict__ Wr,
                                 const float* __restrict__ bl) {
    __shared__ float tile[40][33];
    int tid = threadIdx.x;
    int dcb = blockIdx.x >> 5;
    int kb  = blockIdx.x & 31;
    int dc0 = dcb * 40, k0 = kb * 32, j0 = dcb * 8;
    for (int e = tid; e < 1280; e += 256) {
        int jj = e & 7, g = (e >> 3) % 5, k = e / 40;
        int sc = g * SZ + j0 + jj;
        int kk = k0 + k;
        float v = (kk < SZ) ? Wl[(size_t)kk * GN + sc] : Wr[(size_t)(kk - SZ) * GN + sc];
        tile[5 * jj + g][k] = v;
    }
    __syncthreads();
    for (int e = tid; e < 1280; e += 256) {
        int kk = e & 31, dcl = e >> 5;
        g_Wt[((size_t)(dc0 + dcl) << 10) + k0 + kk] = __float2half(tile[dcl][kk]);
    }
    if (kb == 0 && tid < 40) {
        int dc = dc0 + tid, j = dc / 5, g = dc % 5;
        g_bias[dc] = bl[g * SZ + j];
    }
}

// ---------------- schedule: smem stacks + flags + barrier reset ----------------
__global__ void schedule_kernel(const int* __restrict__ trans, int T) {
    __shared__ int st[136][33];
    int lt = threadIdx.x;
    int b = blockIdx.x * 32 + lt;
    if (blockIdx.x == 0 && lt < 4) g_bar4[lt] = 0;
    for (int i = 0; i < 136; i++) st[i][lt] = 128;
    int ptr = 0, bptr = 0, nr = 0;
    for (int t = 0; t < T; t++) {
        int tr = trans[b * T + t];
        if (tr == 0) {                                   // SHIFT
            int n = (bptr < NLEAF - 1) ? bptr : (NLEAF - 1);
            int wp = ptr; if (wp < 0) wp = 0; if (wp > 130) wp = 130;
            st[wp][lt] = n;
            ptr++; bptr++;
        } else if (tr == 1) {                            // REDUCE
            int lp = ptr - 2; if (lp < 0) lp = 0;
            int rp = ptr - 1; if (rp < 0) rp = 0;
            if (nr < RMAX) {
                int lv = st[lp][lt], rv = st[rp][lt];
                g_lop[(b << 6) + nr] = lv;
                g_rop[(b << 6) + nr] = rv;
                if (rv >= 64 && rv < 128) atomicOr(&g_badR[nr], 1);
                st[lp][lt] = 64 + nr;
                nr++;
            }
            ptr--;
        }
    }
    g_nred[b] = nr;
    int tp = ptr - 1; if (tp < 0) tp = 0; if (tp > 130) tp = 130;
    g_top[b] = st[tp][lt];
}

// ---------------- PR precompute: PR[row][dc] = leaf_h[row] @ Wr, K=512 ----------------
// grid (16, 128), 256 threads = 8 warps (4m x 2n), tile 128 x 160
__global__ __launch_bounds__(256, 1) void pr_kernel() {
    extern __shared__ __align__(16) char smem[];
    uint32_t sb = (uint32_t)__cvta_generic_to_shared(smem);
    int tid = threadIdx.x, warp = tid >> 5, lane = tid & 31;
    int wm = warp >> 1, wn = warp & 1;
    int wr = wm * 32, wc = wn * 80;
    int row0 = blockIdx.y * 128, col0 = blockIdx.x * 160;

    // resident B: 160 rows x 1024B (Wr slice: k 512..1023), XOR-8 swizzle
    for (int idx = tid; idx < 160 * 64; idx += 256) {
        int r = idx >> 6, c = idx & 63;
        cp16(sb + PR_BOFF + (uint32_t)(r * 1024 + (((c ^ (r & 7)) << 4))),
             (const char*)g_Wt + ((size_t)(col0 + r) << 11) + 1024 + c * 16);
    }
    cp_commit(); cp_wait<0>(); __syncthreads();

    auto issue = [&](int s) {
        uint32_t base = sb + (uint32_t)(s % 3) * 16384;
        #pragma unroll
        for (int j = 0; j < 4; j++) {
            int idx = tid * 4 + j;
            int r = idx >> 3, c = idx & 7;
            int grow = row0 + r;
            const __half* src = &g_h[grow >> 6][grow & 63][s * 64 + c * 8];
            cp16(base + (uint32_t)(r * 128 + (((c ^ (r & 7)) << 4))), src);
        }
    };

    float acc[2][10][4];
    #pragma unroll
    for (int su = 0; su < 2; su++)
        #pragma unroll
        for (int f = 0; f < 10; f++)
            #pragma unroll
            for (int q = 0; q < 4; q++) acc[su][f][q] = 0.0f;

    issue(0); cp_commit();
    issue(1); cp_commit();

    int fr0 = wr + (lane & 7) + ((lane >> 3) & 1) * 8;
    int fr1 = fr0 + 16;
    for (int s = 0; s < 8; s++) {
        cp_wait<1>();
        __syncthreads();
        uint32_t ab = sb + (uint32_t)(s % 3) * 16384;
        #pragma unroll
        for (int i = 0; i < 4; i++) {
            int ca = i * 2 + ((lane >> 4) & 1);
            uint32_t a0[4], a1[4];
            ldsm4(a0, ab + (uint32_t)(fr0 * 128 + (((ca ^ (fr0 & 7)) << 4))));
            ldsm4(a1, ab + (uint32_t)(fr1 * 128 + (((ca ^ (fr1 & 7)) << 4))));
            #pragma unroll
            for (int f = 0; f < 10; f++) {
                int br = wc + f * 8 + (lane & 7);
                int cb = (s * 4 + i) * 2 + ((lane >> 3) & 1);
                uint32_t b0, b1;
                ldsm2(b0, b1, sb + PR_BOFF + (uint32_t)(br * 1024 + (((cb ^ (br & 7)) << 4))));
                mma16816(acc[0][f], a0, b0, b1);
                mma16816(acc[1][f], a1, b0, b1);
            }
        }
        if (s + 2 < 8) issue(s + 2);
        cp_commit();
    }
    cp_wait<0>();

    int gp = lane >> 2, t4 = lane & 3;
    #pragma unroll
    for (int su = 0; su < 2; su++)
        #pragma unroll
        for (int f = 0; f < 10; f++) {
            int r = row0 + wr + su * 16 + gp;
            int c = col0 + wc + f * 8 + t4 * 2;
            *(float2*)&g_PR[(size_t)r * GN + c] = make_float2(acc[su][f][0], acc[su][f][1]);
            *(float2*)&g_PR[(size_t)(r + 8) * GN + c] = make_float2(acc[su][f][2], acc[su][f][3]);
        }
}

// ---------------- persistent SPINN kernel ----------------
// grid (32, 4) = 128 CTAs, 512 threads = 16 warps: kg(4) x wm(2) x wn(2)
__global__ __launch_bounds__(NTH, 1) void spinn_kernel(const float* __restrict__ buffers, int RL) {
    extern __shared__ __align__(16) char smem[];
    uint32_t sb = (uint32_t)__cvta_generic_to_shared(smem);
    const __half** s_lh = (const __half**)(smem + OLH);
    const __half** s_rh = (const __half**)(smem + ORH);
    const float**  s_lc = (const float**)(smem + OLC);
    const float**  s_rc = (const float**)(smem + ORC);
    int* s_rop   = (int*)(smem + OROP);
    int* s_valid = (int*)(smem + OVAL);

    int tid = threadIdx.x, warp = tid >> 5, lane = tid & 31;
    int kg = warp >> 2, wm = (warp >> 1) & 1, wn = warp & 1;
    int wr = wm * 32, wc = wn * 40;
    int row0 = blockIdx.y * BM, col0 = blockIdx.x * BN;
    int by = blockIdx.y;

    // ---- resident B1 (Wl k0..511) and B2 (Wr k512..1023): 80 rows x 1024B each ----
    for (int idx = tid; idx < 80 * 64; idx += NTH) {
        int r = idx >> 6, c = idx & 63;
        uint32_t dsw = (uint32_t)(r * 1024 + (((c ^ (r & 7)) << 4)));
        const char* src = (const char*)g_Wt + ((size_t)(col0 + r) << 11) + c * 16;
        cp16(sb + B1OFF + dsw, src);
        cp16(sb + B2OFF + dsw, src + 1024);
    }
    cp_commit(); cp_wait<0>(); __syncthreads();

    // epilogue constants
    int jl = tid & 15;
    int jg0 = blockIdx.x * 16 + jl;
    float bias[5];
    #pragma unroll
    for (int g = 0; g < 5; g++) bias[g] = g_bias[col0 + jl * 5 + g];

    // A producer: 64 rows x 64 chunks; thread: row tid>>3, chunks (tid&7)+8j
    int arow = tid >> 3, ac0 = tid & 7;

    // fragment rows
    int fr0 = wr + (lane & 7) + ((lane >> 3) & 1) * 8;
    int fr1 = fr0 + 16;
    int gp = lane >> 2, t4 = lane & 3;

    float (*Gs)[BN + 1] = (float (*)[BN + 1])smem;   // reuses A region

    for (int k = 0; k < RL; k++) {
        int v = 0;
        if (tid < BM) {
            int b = row0 + tid;
            int lop = g_lop[(b << 6) + k];
            int rop = g_rop[(b << 6) + k];
            s_lh[tid] = &g_h[b][lop][0];
            s_rh[tid] = &g_h[b][rop][0];
            s_lc[tid] = (lop < 64)  ? (buffers + ((size_t)b << 16) + ((size_t)lop << 10) + SZ)
                      : (lop < 128) ? &g_c[b][lop - 64][0] : &g_c[b][RMAX][0];
            s_rc[tid] = (rop < 64)  ? (buffers + ((size_t)b << 16) + ((size_t)rop << 10) + SZ)
                      : (rop < 128) ? &g_c[b][rop - 64][0] : &g_c[b][RMAX][0];
            s_rop[tid] = rop;
            v = s_valid[tid] = (k < g_nred[b]) ? 1 : 0;
        }
        if (__syncthreads_or(v)) {
            int skipf = (g_badR[k] == 0);

            auto loadA = [&](const __half* src) {
                #pragma unroll
                for (int j = 0; j < 8; j++) {
                    int c = ac0 + j * 8;
                    cp16(sb + AOFF + (uint32_t)(arow * 1024 + (((c ^ (arow & 7)) << 4))),
                         src + c * 8);
                }
                cp_commit();
            };

            float acc[2][5][4];
            #pragma unroll
            for (int su = 0; su < 2; su++)
                #pragma unroll
                for (int f = 0; f < 5; f++)
                    #pragma unroll
                    for (int q = 0; q < 4; q++) acc[su][f][q] = 0.0f;

            auto pass = [&](uint32_t boff) {
                #pragma unroll
                for (int i = 0; i < 8; i++) {
                    int ca = kg * 16 + i * 2 + ((lane >> 4) & 1);
                    uint32_t a0[4], a1[4];
                    ldsm4(a0, sb + AOFF + (uint32_t)(fr0 * 1024 + (((ca ^ (fr0 & 7)) << 4))));
                    ldsm4(a1, sb + AOFF + (uint32_t)(fr1 * 1024 + (((ca ^ (fr1 & 7)) << 4))));
                    #pragma unroll
                    for (int f = 0; f < 5; f++) {
                        int br = wc + f * 8 + (lane & 7);
                        int cb = kg * 16 + i * 2 + ((lane >> 3) & 1);
                        uint32_t b0, b1;
                        ldsm2(b0, b1, sb + boff + (uint32_t)(br * 1024 + (((cb ^ (br & 7)) << 4))));
                        mma16816(acc[0][f], a0, b0, b1);
                        mma16816(acc[1][f], a1, b0, b1);
                    }
                }
            };

            loadA(s_lh[arow]);
            cp_wait<0>();
            __syncthreads();
            pass(B1OFF);

            if (!skipf) {                 // generic fallback: rh @ Wr in-step
                __syncthreads();
                loadA(s_rh[arow]);
                cp_wait<0>();
                __syncthreads();
                pass(B2OFF);
            }
            __syncthreads();              // A reads done before Gs reuse

            // ---- K-split reduction (4 passes) ----
            #pragma unroll
            for (int pass4 = 3; pass4 >= 0; pass4--) {
                if (kg == pass4) {
                    #pragma unroll
                    for (int su = 0; su < 2; su++)
                        #pragma unroll
                        for (int f = 0; f < 5; f++) {
                            int rr = wr + su * 16 + gp, cc = wc + f * 8 + t4 * 2;
                            if (pass4 == 3) {
                                Gs[rr][cc]         = acc[su][f][0];
                                Gs[rr][cc + 1]     = acc[su][f][1];
                                Gs[rr + 8][cc]     = acc[su][f][2];
                                Gs[rr + 8][cc + 1] = acc[su][f][3];
                            } else {
                                Gs[rr][cc]         += acc[su][f][0];
                                Gs[rr][cc + 1]     += acc[su][f][1];
                                Gs[rr + 8][cc]     += acc[su][f][2];
                                Gs[rr + 8][cc + 1] += acc[su][f][3];
                            }
                        }
                }
                __syncthreads();
            }

            // ---- LSTM epilogue ----
            #pragma unroll
            for (int i = 0; i < 2; i++) {
                int r = (tid >> 4) + i * 32;
                if (s_valid[r]) {
                    int b  = row0 + r;
                    int cb = jl * 5;
                    float tab[5] = {0.f, 0.f, 0.f, 0.f, 0.f};
                    if (skipf) {
                        int rp = s_rop[r];
                        if (rp < 64) {
                            const float* tp = &g_PR[((size_t)((b << 6) + rp)) * GN + col0 + cb];
                            #pragma unroll
                            for (int g = 0; g < 5; g++) tab[g] = tp[g];
                        }
                    }
                    float a  = Gs[r][cb + 0] + bias[0] + tab[0];
                    float ii = Gs[r][cb + 1] + bias[1] + tab[1];
                    float f1 = Gs[r][cb + 2] + bias[2] + tab[2];
                    float f2 = Gs[r][cb + 3] + bias[3] + tab[3];
                    float o  = Gs[r][cb + 4] + bias[4] + tab[4];
                    float lc = s_lc[r][jg0];
                    float rc = s_rc[r][jg0];
                    float cc = tanhf(a) * sigm(ii) + sigm(f1) * lc + sigm(f2) * rc;
                    float hh = sigm(o) * tanhf(cc);
                    g_h[b][64 + k][jg0] = __float2half(hh);
                    g_hf[b][k][jg0]     = hh;
                    g_c[b][k][jg0]      = cc;
                }
            }
        }

        // ---- row-group barrier (32 CTAs) ----
        __syncthreads();
        __threadfence();
        if (tid == 0) {
            atomicAdd(&g_bar4[by], 1u);
            unsigned tgt = (unsigned)(32 * (k + 1));
            while (*((volatile unsigned*)&g_bar4[by]) < tgt) { }
        }
        __syncthreads();
        __threadfence();
    }
}

// ---------------- final gather ----------------
__global__ void final_kernel(const float* __restrict__ buffers, float* __restrict__ out) {
    int i = blockIdx.x * blockDim.x + threadIdx.x;
    if (i >= BSZ * SZ) return;
    int b = i / SZ, j = i % SZ;
    int op = g_top[b];
    float v;
    if (op < 64)       v = buffers[((size_t)b << 16) + ((size_t)op << 10) + j];
    else if (op < 128) v = g_hf[b][op - 64][j];
    else               v = 0.0f;
    out[i] = v;
}

// ---------------- launch ----------------
extern "C" void kernel_launch(void* const* d_in, const int* in_sizes, int n_in,
                              void* d_out, int out_size) {
    const float* buffers = (const float*)d_in[0];
    const int*   trans   = (const int*)d_in[1];
    const float* Wl      = (const float*)d_in[2];
    const float* Wr      = (const float*)d_in[3];
    const float* bl      = (const float*)d_in[4];
    float*       out     = (float*)d_out;

    int T  = in_sizes[1] / BSZ;
    int RL = (T + 1) / 2;
    if (RL > RMAX) RL = RMAX;

    static int attr_done = 0;
    if (!attr_done) {
        cudaFuncSetAttribute(spinn_kernel, cudaFuncAttributeMaxDynamicSharedMemorySize,
                             SMEM_TOTAL);
        cudaFuncSetAttribute(pr_kernel, cudaFuncAttributeMaxDynamicSharedMemorySize,
                             PR_SMEM);
        attr_done = 1;
    }

    schedule_kernel<<<8, 32>>>(trans, T);
    setup_kernel<<<8192 + 512, 256>>>(buffers);
    convert_w_kernel<<<2048, 256>>>(Wl, Wr, bl);

    dim3 prgrid(GN / 160, (BSZ * NLEAF) / 128);   // (16, 128)
    pr_kernel<<<prgrid, 256, PR_SMEM>>>();

    dim3 grid(GN / BN, BSZ / BM);                 // (32, 4) = 128 CTAs
    spinn_kernel<<<grid, NTH, SMEM_TOTAL>>>(buffers, RL);

    final_kernel<<<(BSZ * SZ + 255) / 256, 256>>>(buffers, out);
}

// round 8
// speedup vs baseline: 1.4000x; 1.2210x over previous
#include <cuda_runtime.h>
#include <cuda_fp16.h>
#include <cstdint>
#include <math.h>

#define BSZ   256
#define NLEAF 64
#define SZ    512
#define D2    1024
#define GN    2560
#define RMAX  64

#define BM    64
#define BN    80
#define NTH   512

// spinn smem layout (bytes): A(64K, also Gs0/Gs1) | B1(Wl) | B2(Wr) | id tables
#define AOFF   0
#define B1OFF  65536
#define B2OFF  147456
#define CTRL   229376
#define SMEM_TOTAL (CTRL + 1536)     // 230912 <= 232448 opt-in max

// pr smem: 3 A stages (80B-stride rows) + resident B
#define PRA    0
#define PRASTG 10240                 // 128 rows x 80B
#define PRB    30720
#define PR_SMEM (PRB + 81920)        // 112640 (2 CTAs/SM)

// ---------------- device scratch ----------------
__device__ __half   g_h[BSZ][129][SZ];      // 0..63 leaves, 64..127 results, 128 zero
__device__ float    g_c[BSZ][RMAX + 1][SZ];
__device__ float    g_hf[BSZ][RMAX][SZ];
__device__ __half   g_Wt[(size_t)GN * D2];  // [dc][k] gate-interleaved, transposed
__device__ float    g_bias[GN];
__device__ __half   g_PRh[(size_t)BSZ * NLEAF * GN]; // leaf @ Wr (fp16)
__device__ int      g_lop[BSZ * RMAX];
__device__ int      g_rop[BSZ * RMAX];
__device__ int      g_nred[BSZ];
__device__ int      g_nredmax[4];
__device__ int      g_top[BSZ];
__device__ int      g_badR[RMAX];
__device__ unsigned g_bar4[4];

__device__ __forceinline__ float sigm(float x) { return 1.0f / (1.0f + expf(-x)); }

// ---------------- PTX helpers ----------------
__device__ __forceinline__ void cp16(uint32_t sdst, const void* gsrc) {
    asm volatile("cp.async.cg.shared.global [%0], [%1], 16;\n" :: "r"(sdst), "l"(gsrc));
}
__device__ __forceinline__ void cp_commit() { asm volatile("cp.async.commit_group;\n" ::); }
template <int N> __device__ __forceinline__ void cp_wait() {
    asm volatile("cp.async.wait_group %0;\n" :: "n"(N));
}
__device__ __forceinline__ void ldsm4(uint32_t* r, uint32_t addr) {
    asm volatile("ldmatrix.sync.aligned.m8n8.x4.shared.b16 {%0,%1,%2,%3},[%4];\n"
                 : "=r"(r[0]), "=r"(r[1]), "=r"(r[2]), "=r"(r[3]) : "r"(addr));
}
__device__ __forceinline__ void ldsm2(uint32_t& r0, uint32_t& r1, uint32_t addr) {
    asm volatile("ldmatrix.sync.aligned.m8n8.x2.shared.b16 {%0,%1},[%2];\n"
                 : "=r"(r0), "=r"(r1) : "r"(addr));
}
__device__ __forceinline__ void mma16816(float* c, const uint32_t* a, uint32_t b0, uint32_t b1) {
    asm volatile(
        "mma.sync.aligned.m16n8k16.row.col.f32.f16.f16.f32 "
        "{%0,%1,%2,%3},{%4,%5,%6,%7},{%8,%9},{%0,%1,%2,%3};\n"
        : "+f"(c[0]), "+f"(c[1]), "+f"(c[2]), "+f"(c[3])
        : "r"(a[0]), "r"(a[1]), "r"(a[2]), "r"(a[3]), "r"(b0), "r"(b1));
}

// ---------------- setup: leaves->fp16 + zero slots ----------------
__global__ void setup_kernel(const float* __restrict__ buffers) {
    int bid = blockIdx.x, tid = threadIdx.x;
    if (bid < 8192) {
        int i4 = (bid * 256 + tid) * 4;
        int b = i4 >> 15, rem = i4 & 32767;
        int r = rem >> 9, j = rem & 511;
        float4 v = *(const float4*)(buffers + ((size_t)b << 16) + ((size_t)r << 10) + j);
        __half2 h0 = __floats2half2_rn(v.x, v.y);
        __half2 h1 = __floats2half2_rn(v.z, v.w);
        *(uint2*)&g_h[b][r][j] = make_uint2(*(uint32_t*)&h0, *(uint32_t*)&h1);
    } else {
        int i = (bid - 8192) * 256 + tid;
        int b = i >> 9, j = i & 511;
        g_h[b][128][j] = __half(0.0f);
        g_c[b][RMAX][j] = 0.0f;
    }
}

// ---------------- weights: fp32 -> fp16, gate-interleave + transpose ----------------
__global__ void convert_w_kernel(const float* __restrict__ Wl,
                                 const float* __restrict__ Wr,
                                 const float* __restrict__ bl) {
    __shared__ float tile[40][33];
    int tid = threadIdx.x;
    int dcb = blockIdx.x >> 5;
    int kb  = blockIdx.x & 31;
    int dc0 = dcb * 40, k0 = kb * 32, j0 = dcb * 8;
    for (int e = tid; e < 1280; e += 256) {
        int jj = e & 7, g = (e >> 3) % 5, k = e / 40;
        int sc = g * SZ + j0 + jj;
        int kk = k0 + k;
        float v = (kk < SZ) ? Wl[(size_t)kk * GN + sc] : Wr[(size_t)(kk - SZ) * GN + sc];
        tile[5 * jj + g][k] = v;
    }
    __syncthreads();
    for (int e = tid; e < 1280; e += 256) {
        int kk = e & 31, dcl = e >> 5;
        g_Wt[((size_t)(dc0 + dcl) << 10) + k0 + kk] = __float2half(tile[dcl][kk]);
    }
    if (kb == 0 && tid < 40) {
        int dc = dc0 + tid, j = dc / 5, g = dc % 5;
        g_bias[dc] = bl[g * SZ + j];
    }
}

// ---------------- schedule ----------------
__global__ void schedule_kernel(const int* __restrict__ trans, int T) {
    __shared__ int st[136][33];
    int lt = threadIdx.x;
    int b = blockIdx.x * 32 + lt;
    if (blockIdx.x == 0 && lt < 4) g_bar4[lt] = 0;
    for (int i = 0; i < 136; i++) st[i][lt] = 128;
    int ptr = 0, bptr = 0, nr = 0;
    for (int t = 0; t < T; t++) {
        int tr = trans[b * T + t];
        if (tr == 0) {
            int n = (bptr < NLEAF - 1) ? bptr : (NLEAF - 1);
            int wp = ptr; if (wp < 0) wp = 0; if (wp > 130) wp = 130;
            st[wp][lt] = n;
            ptr++; bptr++;
        } else if (tr == 1) {
            int lp = ptr - 2; if (lp < 0) lp = 0;
            int rp = ptr - 1; if (rp < 0) rp = 0;
            if (nr < RMAX) {
                int lv = st[lp][lt], rv = st[rp][lt];
                g_lop[(b << 6) + nr] = lv;
                g_rop[(b << 6) + nr] = rv;
                if (rv >= 64 && rv < 128) atomicOr(&g_badR[nr], 1);
                st[lp][lt] = 64 + nr;
                nr++;
            }
            ptr--;
        }
    }
    for (int i = nr; i < RMAX; i++) {      // pad: zero-item ids (safe addresses)
        g_lop[(b << 6) + i] = 128;
        g_rop[(b << 6) + i] = 128;
    }
    g_nred[b] = nr;
    atomicMax(&g_nredmax[b >> 6], nr);
    int tp = ptr - 1; if (tp < 0) tp = 0; if (tp > 130) tp = 130;
    g_top[b] = st[tp][lt];
}

// ---------------- PR precompute: PR[row] = leaf_h[row] @ Wr (fp16 out) ----------------
// grid (32, 128), 256 thr, 8 warps 4m x 2n, tile 128 x 80, K=512, 2 CTAs/SM
__global__ __launch_bounds__(256, 2) void pr_kernel() {
    extern __shared__ __align__(16) char smem[];
    uint32_t sb = (uint32_t)__cvta_generic_to_shared(smem);
    int tid = threadIdx.x, warp = tid >> 5, lane = tid & 31;
    int wm = warp >> 1, wn = warp & 1;
    int wc = wn * 40;
    int row0 = blockIdx.y * 128, col0 = blockIdx.x * 80;

    auto issueA = [&](int s) {     // stage: 128 rows x 32 halfs (64B) at 80B stride
        uint32_t base = sb + PRA + (uint32_t)(s % 3) * PRASTG;
        #pragma unroll
        for (int j = 0; j < 2; j++) {
            int idx = tid + j * 256;
            int r = idx >> 2, c = idx & 3;
            int grow = row0 + r;
            cp16(base + (uint32_t)(r * 80 + c * 16),
                 &g_h[grow >> 6][grow & 63][s * 32 + c * 8]);
        }
    };

    // resident B (Wr half, k 512..1023): 80 rows x 1024B, XOR-8 swizzle  (+ stage0)
    for (int idx = tid; idx < 5120; idx += 256) {
        int r = idx >> 6, c = idx & 63;
        cp16(sb + PRB + (uint32_t)(r * 1024 + (((c ^ (r & 7)) << 4))),
             (const char*)g_Wt + ((size_t)(col0 + r) << 11) + 1024 + c * 16);
    }
    issueA(0); cp_commit();
    issueA(1); cp_commit();

    float acc[2][5][4];
    #pragma unroll
    for (int su = 0; su < 2; su++)
        #pragma unroll
        for (int f = 0; f < 5; f++)
            #pragma unroll
            for (int q = 0; q < 4; q++) acc[su][f][q] = 0.0f;

    int fr0 = wm * 32 + (lane & 7) + ((lane >> 3) & 1) * 8;
    int fr1 = fr0 + 16;
    int sel4 = (lane >> 4) & 1, sel3 = (lane >> 3) & 1;

    for (int s = 0; s < 16; s++) {
        cp_wait<1>();
        __syncthreads();
        uint32_t ab = sb + PRA + (uint32_t)(s % 3) * PRASTG;
        #pragma unroll
        for (int i = 0; i < 2; i++) {
            int ca = i * 2 + sel4;
            uint32_t a0[4], a1[4];
            ldsm4(a0, ab + (uint32_t)(fr0 * 80 + ca * 16));
            ldsm4(a1, ab + (uint32_t)(fr1 * 80 + ca * 16));
            int cbu = (s * 2 + i) * 2 + sel3;
            int br01 = wc + (0 + sel4) * 8 + (lane & 7);
            int br23 = wc + (2 + sel4) * 8 + (lane & 7);
            int br4  = wc + 32 + (lane & 7);
            uint32_t b01[4], b23[4], b4a, b4b;
            ldsm4(b01, sb + PRB + (uint32_t)(br01 * 1024 + (((cbu ^ (br01 & 7)) << 4))));
            ldsm4(b23, sb + PRB + (uint32_t)(br23 * 1024 + (((cbu ^ (br23 & 7)) << 4))));
            ldsm2(b4a, b4b, sb + PRB + (uint32_t)(br4 * 1024 + (((cbu ^ (br4 & 7)) << 4))));
            mma16816(acc[0][0], a0, b01[0], b01[1]); mma16816(acc[1][0], a1, b01[0], b01[1]);
            mma16816(acc[0][1], a0, b01[2], b01[3]); mma16816(acc[1][1], a1, b01[2], b01[3]);
            mma16816(acc[0][2], a0, b23[0], b23[1]); mma16816(acc[1][2], a1, b23[0], b23[1]);
            mma16816(acc[0][3], a0, b23[2], b23[3]); mma16816(acc[1][3], a1, b23[2], b23[3]);
            mma16816(acc[0][4], a0, b4a, b4b);       mma16816(acc[1][4], a1, b4a, b4b);
        }
        if (s + 2 < 16) issueA(s + 2);
        cp_commit();
    }
    cp_wait<0>();

    int gp = lane >> 2, t4 = lane & 3;
    #pragma unroll
    for (int su = 0; su < 2; su++)
        #pragma unroll
        for (int f = 0; f < 5; f++) {
            int r = row0 + wm * 32 + su * 16 + gp;
            int c = col0 + wc + f * 8 + t4 * 2;
            __half2 lo = __floats2half2_rn(acc[su][f][0], acc[su][f][1]);
            __half2 hi = __floats2half2_rn(acc[su][f][2], acc[su][f][3]);
            *(__half2*)&g_PRh[(size_t)r * GN + c]       = lo;
            *(__half2*)&g_PRh[(size_t)(r + 8) * GN + c] = hi;
        }
}

// ---------------- persistent SPINN kernel ----------------
// grid (32, 4) = 128 CTAs, 512 threads = 16 warps: kg(4) x wm(2) x wn(2)
__global__ __launch_bounds__(NTH, 1) void spinn_kernel(const float* __restrict__ buffers, int RL) {
    extern __shared__ __align__(16) char smem[];
    uint32_t sb = (uint32_t)__cvta_generic_to_shared(smem);
    int* s_lop = (int*)(smem + CTRL);          // [2][64]
    int* s_rop = (int*)(smem + CTRL + 512);    // [2][64]
    int* s_val = (int*)(smem + CTRL + 1024);   // [2][64]

    int tid = threadIdx.x, warp = tid >> 5, lane = tid & 31;
    int kg = warp >> 2, wm = (warp >> 1) & 1, wn = warp & 1;
    int wr = wm * 32, wc = wn * 40;
    int row0 = blockIdx.y * BM, col0 = blockIdx.x * BN;
    int by = blockIdx.y;

    // resident B1 (Wl) and B2 (Wr): 80 rows x 1024B each, XOR-8 swizzle
    for (int idx = tid; idx < 80 * 64; idx += NTH) {
        int r = idx >> 6, c = idx & 63;
        uint32_t dsw = (uint32_t)(r * 1024 + (((c ^ (r & 7)) << 4)));
        const char* src = (const char*)g_Wt + ((size_t)(col0 + r) << 11) + c * 16;
        cp16(sb + B1OFF + dsw, src);
        cp16(sb + B2OFF + dsw, src + 1024);
    }
    cp_commit(); cp_wait<0>();

    int RLg = g_nredmax[by];
    if (RLg > RL) RLg = RL;

    // epilogue constants
    int jl = tid & 15;
    int jg0 = blockIdx.x * 16 + jl;
    float bias[5];
    #pragma unroll
    for (int g = 0; g < 5; g++) bias[g] = g_bias[col0 + jl * 5 + g];

    // A producer: row arow, 8 x 16B units
    int arow = tid >> 3, ac0 = tid & 7;
    // fragment addressing
    int fr0 = wr + (lane & 7) + ((lane >> 3) & 1) * 8;
    int fr1 = fr0 + 16;
    int sel4 = (lane >> 4) & 1, sel3 = (lane >> 3) & 1;
    int gp = lane >> 2, t4 = lane & 3;

    float (*Gs0)[84] = (float (*)[84])smem;
    float (*Gs1)[84] = (float (*)[84])(smem + 32768);

    // step-0 id tables
    if (tid < 64) {
        int b = row0 + tid;
        s_lop[tid] = g_lop[b << 6];
        s_rop[tid] = g_rop[b << 6];
        s_val[tid] = (0 < g_nred[b]) ? 1 : 0;
    }
    __syncthreads();

    for (int k = 0; k < RLg; k++) {
        int par = k & 1;
        int skipf = (g_badR[k] == 0);

        auto loadA = [&](int useR) {
            int id = (useR ? s_rop : s_lop)[par * 64 + arow];
            const __half* src = &g_h[row0 + arow][id][0];
            #pragma unroll
            for (int j = 0; j < 8; j++) {
                int c = ac0 + j * 8;
                cp16(sb + AOFF + (uint32_t)(arow * 1024 + (((c ^ (arow & 7)) << 4))),
                     src + c * 8);
            }
            cp_commit();
        };

        loadA(0);

        // ---- prefetch epilogue operands (latency hidden behind GEMM) ----
        float lcv[2], rcv[2], tab[2][5];
        #pragma unroll
        for (int i = 0; i < 2; i++) {
            int r = (tid >> 4) + 32 * i;
            int b = row0 + r;
            int lid = s_lop[par * 64 + r], rid = s_rop[par * 64 + r];
            lcv[i] = (lid < 64) ? buffers[((size_t)b << 16) + ((size_t)lid << 10) + SZ + jg0]
                                : g_c[b][(lid == 128) ? RMAX : (lid - 64)][jg0];
            rcv[i] = (rid < 64) ? buffers[((size_t)b << 16) + ((size_t)rid << 10) + SZ + jg0]
                                : g_c[b][(rid == 128) ? RMAX : (rid - 64)][jg0];
            #pragma unroll
            for (int g = 0; g < 5; g++) tab[i][g] = 0.0f;
            if (skipf && rid < 64) {
                const __half* tp = &g_PRh[((size_t)((b << 6) + rid)) * GN + col0 + jl * 5];
                #pragma unroll
                for (int g = 0; g < 5; g++) tab[i][g] = __half2float(tp[g]);
            }
        }

        // ---- next-step id tables (static schedule; overlap with GEMM) ----
        if (tid < 64) {
            int kn = k + 1;
            int b = row0 + tid;
            int lop = 128, rop = 128, vv = 0;
            if (kn < RMAX) {
                lop = g_lop[(b << 6) + kn];
                rop = g_rop[(b << 6) + kn];
                vv  = (kn < g_nred[b]) ? 1 : 0;
            }
            int np = par ^ 1;
            s_lop[np * 64 + tid] = lop;
            s_rop[np * 64 + tid] = rop;
            s_val[np * 64 + tid] = vv;
        }

        float acc[2][5][4];
        #pragma unroll
        for (int su = 0; su < 2; su++)
            #pragma unroll
            for (int f = 0; f < 5; f++)
                #pragma unroll
                for (int q = 0; q < 4; q++) acc[su][f][q] = 0.0f;

        auto pass = [&](uint32_t boff) {
            #pragma unroll
            for (int i = 0; i < 8; i++) {
                int ca = kg * 16 + i * 2 + sel4;
                uint32_t a0[4], a1[4];
                ldsm4(a0, sb + AOFF + (uint32_t)(fr0 * 1024 + (((ca ^ (fr0 & 7)) << 4))));
                ldsm4(a1, sb + AOFF + (uint32_t)(fr1 * 1024 + (((ca ^ (fr1 & 7)) << 4))));
                int cbu = kg * 16 + i * 2 + sel3;
                int br01 = wc + (0 + sel4) * 8 + (lane & 7);
                int br23 = wc + (2 + sel4) * 8 + (lane & 7);
                int br4  = wc + 32 + (lane & 7);
                uint32_t b01[4], b23[4], b4a, b4b;
                ldsm4(b01, sb + boff + (uint32_t)(br01 * 1024 + (((cbu ^ (br01 & 7)) << 4))));
                ldsm4(b23, sb + boff + (uint32_t)(br23 * 1024 + (((cbu ^ (br23 & 7)) << 4))));
                ldsm2(b4a, b4b, sb + boff + (uint32_t)(br4 * 1024 + (((cbu ^ (br4 & 7)) << 4))));
                mma16816(acc[0][0], a0, b01[0], b01[1]); mma16816(acc[1][0], a1, b01[0], b01[1]);
                mma16816(acc[0][1], a0, b01[2], b01[3]); mma16816(acc[1][1], a1, b01[2], b01[3]);
                mma16816(acc[0][2], a0, b23[0], b23[1]); mma16816(acc[1][2], a1, b23[0], b23[1]);
                mma16816(acc[0][3], a0, b23[2], b23[3]); mma16816(acc[1][3], a1, b23[2], b23[3]);
                mma16816(acc[0][4], a0, b4a, b4b);       mma16816(acc[1][4], a1, b4a, b4b);
            }
        };

        cp_wait<0>();
        __syncthreads();
        pass(B1OFF);

        if (!skipf) {                    // generic fallback: rh @ Wr in-step
            __syncthreads();
            loadA(1);
            cp_wait<0>();
            __syncthreads();
            pass(B2OFF);
        }
        __syncthreads();                 // A reads done; reuse region as Gs0/Gs1

        // ---- K-split reduction: 2 buffers, 2 sync points ----
        if (kg >= 2) {
            float (*G)[84] = (kg == 3) ? Gs0 : Gs1;
            #pragma unroll
            for (int su = 0; su < 2; su++)
                #pragma unroll
                for (int f = 0; f < 5; f++) {
                    int rr = wr + su * 16 + gp, cc = wc + f * 8 + t4 * 2;
                    G[rr][cc]         = acc[su][f][0];
                    G[rr][cc + 1]     = acc[su][f][1];
                    G[rr + 8][cc]     = acc[su][f][2];
                    G[rr + 8][cc + 1] = acc[su][f][3];
                }
        }
        __syncthreads();
        if (kg < 2) {
            float (*G)[84] = (kg == 1) ? Gs0 : Gs1;
            #pragma unroll
            for (int su = 0; su < 2; su++)
                #pragma unroll
                for (int f = 0; f < 5; f++) {
                    int rr = wr + su * 16 + gp, cc = wc + f * 8 + t4 * 2;
                    G[rr][cc]         += acc[su][f][0];
                    G[rr][cc + 1]     += acc[su][f][1];
                    G[rr + 8][cc]     += acc[su][f][2];
                    G[rr + 8][cc + 1] += acc[su][f][3];
                }
        }
        __syncthreads();

        // ---- LSTM epilogue ----
        #pragma unroll
        for (int i = 0; i < 2; i++) {
            int r = (tid >> 4) + 32 * i;
            if (s_val[par * 64 + r]) {
                int b  = row0 + r;
                int cb = jl * 5;
                float a  = Gs0[r][cb + 0] + Gs1[r][cb + 0] + bias[0] + tab[i][0];
                float ii = Gs0[r][cb + 1] + Gs1[r][cb + 1] + bias[1] + tab[i][1];
                float f1 = Gs0[r][cb + 2] + Gs1[r][cb + 2] + bias[2] + tab[i][2];
                float f2 = Gs0[r][cb + 3] + Gs1[r][cb + 3] + bias[3] + tab[i][3];
                float o  = Gs0[r][cb + 4] + Gs1[r][cb + 4] + bias[4] + tab[i][4];
                float cc = tanhf(a) * sigm(ii) + sigm(f1) * lcv[i] + sigm(f2) * rcv[i];
                float hh = sigm(o) * tanhf(cc);
                g_h[b][64 + k][jg0] = __float2half(hh);
                g_hf[b][k][jg0]     = hh;
                g_c[b][k][jg0]      = cc;
            }
        }

        // ---- row-group barrier (32 CTAs) ----
        __syncthreads();
        __threadfence();
        if (tid == 0) {
            atomicAdd(&g_bar4[by], 1u);
            unsigned tgt = (unsigned)(32 * (k + 1));
            while (*((volatile unsigned*)&g_bar4[by]) < tgt) { }
        }
        __syncthreads();
        __threadfence();
    }
}

// ---------------- final gather ----------------
__global__ void final_kernel(const float* __restrict__ buffers, float* __restrict__ out) {
    int i = blockIdx.x * blockDim.x + threadIdx.x;
    if (i >= BSZ * SZ) return;
    int b = i / SZ, j = i % SZ;
    int op = g_top[b];
    float v;
    if (op < 64)       v = buffers[((size_t)b << 16) + ((size_t)op << 10) + j];
    else if (op < 128) v = g_hf[b][op - 64][j];
    else               v = 0.0f;
    out[i] = v;
}

// ---------------- launch ----------------
extern "C" void kernel_launch(void* const* d_in, const int* in_sizes, int n_in,
                              void* d_out, int out_size) {
    const float* buffers = (const float*)d_in[0];
    const int*   trans   = (const int*)d_in[1];
    const float* Wl      = (const float*)d_in[2];
    const float* Wr      = (const float*)d_in[3];
    const float* bl      = (const float*)d_in[4];
    float*       out     = (float*)d_out;

    int T  = in_sizes[1] / BSZ;
    int RL = (T + 1) / 2;
    if (RL > RMAX) RL = RMAX;

    static int attr_done = 0;
    if (!attr_done) {
        cudaFuncSetAttribute(spinn_kernel, cudaFuncAttributeMaxDynamicSharedMemorySize,
                             SMEM_TOTAL);
        cudaFuncSetAttribute(pr_kernel, cudaFuncAttributeMaxDynamicSharedMemorySize,
                             PR_SMEM);
        attr_done = 1;
    }

    schedule_kernel<<<8, 32>>>(trans, T);
    setup_kernel<<<8192 + 512, 256>>>(buffers);
    convert_w_kernel<<<2048, 256>>>(Wl, Wr, bl);

    dim3 prgrid(GN / 80, (BSZ * NLEAF) / 128);    // (32, 128)
    pr_kernel<<<prgrid, 256, PR_SMEM>>>();

    dim3 grid(GN / BN, BSZ / BM);                 // (32, 4) = 128 CTAs
    spinn_kernel<<<grid, NTH, SMEM_TOTAL>>>(buffers, RL);

    final_kernel<<<(BSZ * SZ + 255) / 256, 256>>>(buffers, out);
}

// round 9
// speedup vs baseline: 1.4614x; 1.0439x over previous
#include <cuda_runtime.h>
#include <cuda_fp16.h>
#include <cstdint>
#include <math.h>

#define BSZ   256
#define NLEAF 64
#define SZ    512
#define D2    1024
#define GN    2560
#define RMAX  64

#define BM    64
#define BN    80
#define NTH   512

// spinn smem layout (bytes): A(64K, also Gs0/Gs1) | B1(Wl) | B2(Wr) | id tables
#define AOFF   0
#define B1OFF  65536
#define B2OFF  147456
#define CTRL   229376
#define SMEM_TOTAL (CTRL + 1536)     // 230912 <= 232448 opt-in max

// pr smem: 3 A stages (80B-stride rows) + resident B
#define PRA    0
#define PRASTG 10240                 // 128 rows x 80B
#define PRB    30720
#define PR_SMEM (PRB + 81920)        // 112640 (2 CTAs/SM)

// ---------------- device scratch ----------------
__device__ __half   g_h[BSZ][129][SZ];      // 0..63 leaves, 64..127 results, 128 zero
__device__ float    g_c[BSZ][RMAX + 1][SZ];
__device__ float    g_hf[BSZ][RMAX][SZ];
__device__ __half   g_Wt[(size_t)GN * D2];  // [dc][k] gate-interleaved, transposed
__device__ float    g_bias[GN];
__device__ __half   g_PRh[(size_t)BSZ * NLEAF * GN]; // leaf @ Wr (fp16)
__device__ int      g_lop[BSZ * RMAX];
__device__ int      g_rop[BSZ * RMAX];
__device__ int      g_nred[BSZ];
__device__ int      g_nredmax[4];
__device__ int      g_top[BSZ];
__device__ int      g_badR[RMAX];
__device__ unsigned g_bar4[4];

__device__ __forceinline__ float sigm(float x) { return 1.0f / (1.0f + expf(-x)); }

// ---------------- PTX helpers ----------------
__device__ __forceinline__ void cp16(uint32_t sdst, const void* gsrc) {
    asm volatile("cp.async.cg.shared.global [%0], [%1], 16;\n" :: "r"(sdst), "l"(gsrc));
}
__device__ __forceinline__ void cp_commit() { asm volatile("cp.async.commit_group;\n" ::); }
template <int N> __device__ __forceinline__ void cp_wait() {
    asm volatile("cp.async.wait_group %0;\n" :: "n"(N));
}
__device__ __forceinline__ void ldsm4(uint32_t* r, uint32_t addr) {
    asm volatile("ldmatrix.sync.aligned.m8n8.x4.shared.b16 {%0,%1,%2,%3},[%4];\n"
                 : "=r"(r[0]), "=r"(r[1]), "=r"(r[2]), "=r"(r[3]) : "r"(addr));
}
__device__ __forceinline__ void ldsm2(uint32_t& r0, uint32_t& r1, uint32_t addr) {
    asm volatile("ldmatrix.sync.aligned.m8n8.x2.shared.b16 {%0,%1},[%2];\n"
                 : "=r"(r0), "=r"(r1) : "r"(addr));
}
__device__ __forceinline__ void mma16816(float* c, const uint32_t* a, uint32_t b0, uint32_t b1) {
    asm volatile(
        "mma.sync.aligned.m16n8k16.row.col.f32.f16.f16.f32 "
        "{%0,%1,%2,%3},{%4,%5,%6,%7},{%8,%9},{%0,%1,%2,%3};\n"
        : "+f"(c[0]), "+f"(c[1]), "+f"(c[2]), "+f"(c[3])
        : "r"(a[0]), "r"(a[1]), "r"(a[2]), "r"(a[3]), "r"(b0), "r"(b1));
}
// grid.sync-style release arrival + acquire poll (no MEMBAR.GPU drain)
__device__ __forceinline__ void bar_arrive_release(unsigned* addr) {
    asm volatile("red.release.gpu.global.add.u32 [%0], %1;" :: "l"(addr), "r"(1u) : "memory");
}
__device__ __forceinline__ unsigned ld_relaxed(const unsigned* addr) {
    unsigned v;
    asm volatile("ld.relaxed.gpu.global.u32 %0, [%1];" : "=r"(v) : "l"(addr) : "memory");
    return v;
}
__device__ __forceinline__ unsigned ld_acquire(const unsigned* addr) {
    unsigned v;
    asm volatile("ld.acquire.gpu.global.u32 %0, [%1];" : "=r"(v) : "l"(addr) : "memory");
    return v;
}

// ---------------- setup: leaves->fp16 + zero slots ----------------
__global__ void setup_kernel(const float* __restrict__ buffers) {
    int bid = blockIdx.x, tid = threadIdx.x;
    if (bid < 8192) {
        int i4 = (bid * 256 + tid) * 4;
        int b = i4 >> 15, rem = i4 & 32767;
        int r = rem >> 9, j = rem & 511;
        float4 v = *(const float4*)(buffers + ((size_t)b << 16) + ((size_t)r << 10) + j);
        __half2 h0 = __floats2half2_rn(v.x, v.y);
        __half2 h1 = __floats2half2_rn(v.z, v.w);
        *(uint2*)&g_h[b][r][j] = make_uint2(*(uint32_t*)&h0, *(uint32_t*)&h1);
    } else {
        int i = (bid - 8192) * 256 + tid;
        int b = i >> 9, j = i & 511;
        g_h[b][128][j] = __half(0.0f);
        g_c[b][RMAX][j] = 0.0f;
    }
}

// ---------------- weights: fp32 -> fp16, gate-interleave + transpose ----------------
__global__ void convert_w_kernel(const float* __restrict__ Wl,
                                 const float* __restrict__ Wr,
                                 const float* __restrict__ bl) {
    __shared__ float tile[40][33];
    int tid = threadIdx.x;
    int dcb = blockIdx.x >> 5;
    int kb  = blockIdx.x & 31;
    int dc0 = dcb * 40, k0 = kb * 32, j0 = dcb * 8;
    for (int e = tid; e < 1280; e += 256) {
        int jj = e & 7, g = (e >> 3) % 5, k = e / 40;
        int sc = g * SZ + j0 + jj;
        int kk = k0 + k;
        float v = (kk < SZ) ? Wl[(size_t)kk * GN + sc] : Wr[(size_t)(kk - SZ) * GN + sc];
        tile[5 * jj + g][k] = v;
    }
    __syncthreads();
    for (int e = tid; e < 1280; e += 256) {
        int kk = e & 31, dcl = e >> 5;
        g_Wt[((size_t)(dc0 + dcl) << 10) + k0 + kk] = __float2half(tile[dcl][kk]);
    }
    if (kb == 0 && tid < 40) {
        int dc = dc0 + tid, j = dc / 5, g = dc % 5;
        g_bias[dc] = bl[g * SZ + j];
    }
}

// ---------------- schedule ----------------
__global__ void schedule_kernel(const int* __restrict__ trans, int T) {
    __shared__ int st[136][33];
    int lt = threadIdx.x;
    int b = blockIdx.x * 32 + lt;
    if (blockIdx.x == 0 && lt < 4) g_bar4[lt] = 0;
    for (int i = 0; i < 136; i++) st[i][lt] = 128;
    int ptr = 0, bptr = 0, nr = 0;
    for (int t = 0; t < T; t++) {
        int tr = trans[b * T + t];
        if (tr == 0) {
            int n = (bptr < NLEAF - 1) ? bptr : (NLEAF - 1);
            int wp = ptr; if (wp < 0) wp = 0; if (wp > 130) wp = 130;
            st[wp][lt] = n;
            ptr++; bptr++;
        } else if (tr == 1) {
            int lp = ptr - 2; if (lp < 0) lp = 0;
            int rp = ptr - 1; if (rp < 0) rp = 0;
            if (nr < RMAX) {
                int lv = st[lp][lt], rv = st[rp][lt];
                g_lop[(b << 6) + nr] = lv;
                g_rop[(b << 6) + nr] = rv;
                if (rv >= 64 && rv < 128) atomicOr(&g_badR[nr], 1);
                st[lp][lt] = 64 + nr;
                nr++;
            }
            ptr--;
        }
    }
    for (int i = nr; i < RMAX; i++) {
        g_lop[(b << 6) + i] = 128;
        g_rop[(b << 6) + i] = 128;
    }
    g_nred[b] = nr;
    atomicMax(&g_nredmax[b >> 6], nr);
    int tp = ptr - 1; if (tp < 0) tp = 0; if (tp > 130) tp = 130;
    g_top[b] = st[tp][lt];
}

// ---------------- PR precompute: PR[row] = leaf_h[row] @ Wr (fp16 out) ----------------
__global__ __launch_bounds__(256, 2) void pr_kernel() {
    extern __shared__ __align__(16) char smem[];
    uint32_t sb = (uint32_t)__cvta_generic_to_shared(smem);
    int tid = threadIdx.x, warp = tid >> 5, lane = tid & 31;
    int wm = warp >> 1, wn = warp & 1;
    int wc = wn * 40;
    int row0 = blockIdx.y * 128, col0 = blockIdx.x * 80;

    auto issueA = [&](int s) {
        uint32_t base = sb + PRA + (uint32_t)(s % 3) * PRASTG;
        #pragma unroll
        for (int j = 0; j < 2; j++) {
            int idx = tid + j * 256;
            int r = idx >> 2, c = idx & 3;
            int grow = row0 + r;
            cp16(base + (uint32_t)(r * 80 + c * 16),
                 &g_h[grow >> 6][grow & 63][s * 32 + c * 8]);
        }
    };

    for (int idx = tid; idx < 5120; idx += 256) {
        int r = idx >> 6, c = idx & 63;
        cp16(sb + PRB + (uint32_t)(r * 1024 + (((c ^ (r & 7)) << 4))),
             (const char*)g_Wt + ((size_t)(col0 + r) << 11) + 1024 + c * 16);
    }
    issueA(0); cp_commit();
    issueA(1); cp_commit();

    float acc[2][5][4];
    #pragma unroll
    for (int su = 0; su < 2; su++)
        #pragma unroll
        for (int f = 0; f < 5; f++)
            #pragma unroll
            for (int q = 0; q < 4; q++) acc[su][f][q] = 0.0f;

    int fr0 = wm * 32 + (lane & 7) + ((lane >> 3) & 1) * 8;
    int fr1 = fr0 + 16;
    int sel4 = (lane >> 4) & 1, sel3 = (lane >> 3) & 1;

    for (int s = 0; s < 16; s++) {
        cp_wait<1>();
        __syncthreads();
        uint32_t ab = sb + PRA + (uint32_t)(s % 3) * PRASTG;
        #pragma unroll
        for (int i = 0; i < 2; i++) {
            int ca = i * 2 + sel4;
            uint32_t a0[4], a1[4];
            ldsm4(a0, ab + (uint32_t)(fr0 * 80 + ca * 16));
            ldsm4(a1, ab + (uint32_t)(fr1 * 80 + ca * 16));
            int cbu = (s * 2 + i) * 2 + sel3;
            int br01 = wc + (0 + sel4) * 8 + (lane & 7);
            int br23 = wc + (2 + sel4) * 8 + (lane & 7);
            int br4  = wc + 32 + (lane & 7);
            uint32_t b01[4], b23[4], b4a, b4b;
            ldsm4(b01, sb + PRB + (uint32_t)(br01 * 1024 + (((cbu ^ (br01 & 7)) << 4))));
            ldsm4(b23, sb + PRB + (uint32_t)(br23 * 1024 + (((cbu ^ (br23 & 7)) << 4))));
            ldsm2(b4a, b4b, sb + PRB + (uint32_t)(br4 * 1024 + (((cbu ^ (br4 & 7)) << 4))));
            mma16816(acc[0][0], a0, b01[0], b01[1]); mma16816(acc[1][0], a1, b01[0], b01[1]);
            mma16816(acc[0][1], a0, b01[2], b01[3]); mma16816(acc[1][1], a1, b01[2], b01[3]);
            mma16816(acc[0][2], a0, b23[0], b23[1]); mma16816(acc[1][2], a1, b23[0], b23[1]);
            mma16816(acc[0][3], a0, b23[2], b23[3]); mma16816(acc[1][3], a1, b23[2], b23[3]);
            mma16816(acc[0][4], a0, b4a, b4b);       mma16816(acc[1][4], a1, b4a, b4b);
        }
        if (s + 2 < 16) issueA(s + 2);
        cp_commit();
    }
    cp_wait<0>();

    int gp = lane >> 2, t4 = lane & 3;
    #pragma unroll
    for (int su = 0; su < 2; su++)
        #pragma unroll
        for (int f = 0; f < 5; f++) {
            int r = row0 + wm * 32 + su * 16 + gp;
            int c = col0 + wc + f * 8 + t4 * 2;
            __half2 lo = __floats2half2_rn(acc[su][f][0], acc[su][f][1]);
            __half2 hi = __floats2half2_rn(acc[su][f][2], acc[su][f][3]);
            *(__half2*)&g_PRh[(size_t)r * GN + c]       = lo;
            *(__half2*)&g_PRh[(size_t)(r + 8) * GN + c] = hi;
        }
}

// ---------------- persistent SPINN kernel ----------------
// grid (32, 4) = 128 CTAs, 512 threads = 16 warps: kg(4) x wm(2) x wn(2)
__global__ __launch_bounds__(NTH, 1) void spinn_kernel(const float* __restrict__ buffers, int RL) {
    extern __shared__ __align__(16) char smem[];
    uint32_t sb = (uint32_t)__cvta_generic_to_shared(smem);
    int* s_lop = (int*)(smem + CTRL);          // [2][64]
    int* s_rop = (int*)(smem + CTRL + 512);    // [2][64]
    int* s_val = (int*)(smem + CTRL + 1024);   // [2][64]

    int tid = threadIdx.x, warp = tid >> 5, lane = tid & 31;
    int kg = warp >> 2, wm = (warp >> 1) & 1, wn = warp & 1;
    int wr = wm * 32, wc = wn * 40;
    int row0 = blockIdx.y * BM, col0 = blockIdx.x * BN;
    int by = blockIdx.y;

    // resident B1 (Wl) and B2 (Wr): 80 rows x 1024B each, XOR-8 swizzle
    for (int idx = tid; idx < 80 * 64; idx += NTH) {
        int r = idx >> 6, c = idx & 63;
        uint32_t dsw = (uint32_t)(r * 1024 + (((c ^ (r & 7)) << 4)));
        const char* src = (const char*)g_Wt + ((size_t)(col0 + r) << 11) + c * 16;
        cp16(sb + B1OFF + dsw, src);
        cp16(sb + B2OFF + dsw, src + 1024);
    }
    cp_commit(); cp_wait<0>();

    int RLg = g_nredmax[by];
    if (RLg > RL) RLg = RL;

    int jl = tid & 15;
    int jg0 = blockIdx.x * 16 + jl;
    float bias[5];
    #pragma unroll
    for (int g = 0; g < 5; g++) bias[g] = g_bias[col0 + jl * 5 + g];

    int arow = tid >> 3, ac0 = tid & 7;
    int fr0 = wr + (lane & 7) + ((lane >> 3) & 1) * 8;
    int fr1 = fr0 + 16;
    int sel4 = (lane >> 4) & 1, sel3 = (lane >> 3) & 1;
    int gp = lane >> 2, t4 = lane & 3;

    float (*Gs0)[84] = (float (*)[84])smem;
    float (*Gs1)[84] = (float (*)[84])(smem + 32768);

    if (tid < 64) {
        int b = row0 + tid;
        s_lop[tid] = g_lop[b << 6];
        s_rop[tid] = g_rop[b << 6];
        s_val[tid] = (0 < g_nred[b]) ? 1 : 0;
    }
    __syncthreads();

    for (int k = 0; k < RLg; k++) {
        int par = k & 1;
        int skipf = (g_badR[k] == 0);

        auto loadA = [&](int useR) {
            int id = (useR ? s_rop : s_lop)[par * 64 + arow];
            const __half* src = &g_h[row0 + arow][id][0];
            #pragma unroll
            for (int j = 0; j < 8; j++) {
                int c = ac0 + j * 8;
                cp16(sb + AOFF + (uint32_t)(arow * 1024 + (((c ^ (arow & 7)) << 4))),
                     src + c * 8);
            }
            cp_commit();
        };

        loadA(0);

        // ---- prefetch epilogue operands (latency hidden behind GEMM) ----
        float lcv[2], rcv[2], tab[2][5];
        #pragma unroll
        for (int i = 0; i < 2; i++) {
            int r = (tid >> 4) + 32 * i;
            int b = row0 + r;
            int lid = s_lop[par * 64 + r], rid = s_rop[par * 64 + r];
            lcv[i] = (lid < 64) ? buffers[((size_t)b << 16) + ((size_t)lid << 10) + SZ + jg0]
                                : g_c[b][(lid == 128) ? RMAX : (lid - 64)][jg0];
            rcv[i] = (rid < 64) ? buffers[((size_t)b << 16) + ((size_t)rid << 10) + SZ + jg0]
                                : g_c[b][(rid == 128) ? RMAX : (rid - 64)][jg0];
            #pragma unroll
            for (int g = 0; g < 5; g++) tab[i][g] = 0.0f;
            if (skipf && rid < 64) {
                const __half* tp = &g_PRh[((size_t)((b << 6) + rid)) * GN + col0 + jl * 5];
                #pragma unroll
                for (int g = 0; g < 5; g++) tab[i][g] = __half2float(tp[g]);
            }
        }

        // ---- next-step id tables (static schedule; overlap with GEMM) ----
        if (tid < 64) {
            int kn = k + 1;
            int b = row0 + tid;
            int lop = 128, rop = 128, vv = 0;
            if (kn < RMAX) {
                lop = g_lop[(b << 6) + kn];
                rop = g_rop[(b << 6) + kn];
                vv  = (kn < g_nred[b]) ? 1 : 0;
            }
            int np = par ^ 1;
            s_lop[np * 64 + tid] = lop;
            s_rop[np * 64 + tid] = rop;
            s_val[np * 64 + tid] = vv;
        }

        float acc[2][5][4];
        #pragma unroll
        for (int su = 0; su < 2; su++)
            #pragma unroll
            for (int f = 0; f < 5; f++)
                #pragma unroll
                for (int q = 0; q < 4; q++) acc[su][f][q] = 0.0f;

        auto pass = [&](uint32_t boff) {
            #pragma unroll
            for (int i = 0; i < 8; i++) {
                int ca = kg * 16 + i * 2 + sel4;
                uint32_t a0[4], a1[4];
                ldsm4(a0, sb + AOFF + (uint32_t)(fr0 * 1024 + (((ca ^ (fr0 & 7)) << 4))));
                ldsm4(a1, sb + AOFF + (uint32_t)(fr1 * 1024 + (((ca ^ (fr1 & 7)) << 4))));
                int cbu = kg * 16 + i * 2 + sel3;
                int br01 = wc + (0 + sel4) * 8 + (lane & 7);
                int br23 = wc + (2 + sel4) * 8 + (lane & 7);
                int br4  = wc + 32 + (lane & 7);
                uint32_t b01[4], b23[4], b4a, b4b;
                ldsm4(b01, sb + boff + (uint32_t)(br01 * 1024 + (((cbu ^ (br01 & 7)) << 4))));
                ldsm4(b23, sb + boff + (uint32_t)(br23 * 1024 + (((cbu ^ (br23 & 7)) << 4))));
                ldsm2(b4a, b4b, sb + boff + (uint32_t)(br4 * 1024 + (((cbu ^ (br4 & 7)) << 4))));
                mma16816(acc[0][0], a0, b01[0], b01[1]); mma16816(acc[1][0], a1, b01[0], b01[1]);
                mma16816(acc[0][1], a0, b01[2], b01[3]); mma16816(acc[1][1], a1, b01[2], b01[3]);
                mma16816(acc[0][2], a0, b23[0], b23[1]); mma16816(acc[1][2], a1, b23[0], b23[1]);
                mma16816(acc[0][3], a0, b23[2], b23[3]); mma16816(acc[1][3], a1, b23[2], b23[3]);
                mma16816(acc[0][4], a0, b4a, b4b);       mma16816(acc[1][4], a1, b4a, b4b);
            }
        };

        cp_wait<0>();
        __syncthreads();
        pass(B1OFF);

        if (!skipf) {
            __syncthreads();
            loadA(1);
            cp_wait<0>();
            __syncthreads();
            pass(B2OFF);
        }
        __syncthreads();

        // ---- K-split reduction: 2 buffers, 2 sync points ----
        if (kg >= 2) {
            float (*G)[84] = (kg == 3) ? Gs0 : Gs1;
            #pragma unroll
            for (int su = 0; su < 2; su++)
                #pragma unroll
                for (int f = 0; f < 5; f++) {
                    int rr = wr + su * 16 + gp, cc = wc + f * 8 + t4 * 2;
                    G[rr][cc]         = acc[su][f][0];
                    G[rr][cc + 1]     = acc[su][f][1];
                    G[rr + 8][cc]     = acc[su][f][2];
                    G[rr + 8][cc + 1] = acc[su][f][3];
                }
        }
        __syncthreads();
        if (kg < 2) {
            float (*G)[84] = (kg == 1) ? Gs0 : Gs1;
            #pragma unroll
            for (int su = 0; su < 2; su++)
                #pragma unroll
                for (int f = 0; f < 5; f++) {
                    int rr = wr + su * 16 + gp, cc = wc + f * 8 + t4 * 2;
                    G[rr][cc]         += acc[su][f][0];
                    G[rr][cc + 1]     += acc[su][f][1];
                    G[rr + 8][cc]     += acc[su][f][2];
                    G[rr + 8][cc + 1] += acc[su][f][3];
                }
        }
        __syncthreads();

        // ---- LSTM epilogue ----
        #pragma unroll
        for (int i = 0; i < 2; i++) {
            int r = (tid >> 4) + 32 * i;
            if (s_val[par * 64 + r]) {
                int b  = row0 + r;
                int cb = jl * 5;
                float a  = Gs0[r][cb + 0] + Gs1[r][cb + 0] + bias[0] + tab[i][0];
                float ii = Gs0[r][cb + 1] + Gs1[r][cb + 1] + bias[1] + tab[i][1];
                float f1 = Gs0[r][cb + 2] + Gs1[r][cb + 2] + bias[2] + tab[i][2];
                float f2 = Gs0[r][cb + 3] + Gs1[r][cb + 3] + bias[3] + tab[i][3];
                float o  = Gs0[r][cb + 4] + Gs1[r][cb + 4] + bias[4] + tab[i][4];
                float cc = tanhf(a) * sigm(ii) + sigm(f1) * lcv[i] + sigm(f2) * rcv[i];
                float hh = sigm(o) * tanhf(cc);
                g_h[b][64 + k][jg0] = __float2half(hh);
                g_hf[b][k][jg0]     = hh;
                g_c[b][k][jg0]      = cc;
            }
        }

        // ---- row-group barrier: release arrival + acquire poll (no MEMBAR.GPU) ----
        __syncthreads();                 // orders all threads' epilogue STGs before arrival
        if (tid == 0) {
            bar_arrive_release(&g_bar4[by]);
            unsigned tgt = (unsigned)(32 * (k + 1));
            while (ld_relaxed(&g_bar4[by]) < tgt) { }
            (void)ld_acquire(&g_bar4[by]);   // acquire: make peer epilogue writes visible
        }
        __syncthreads();                 // propagate acquire to all threads (CTA scope)
    }
}

// ---------------- final gather ----------------
__global__ void final_kernel(const float* __restrict__ buffers, float* __restrict__ out) {
    int i = blockIdx.x * blockDim.x + threadIdx.x;
    if (i >= BSZ * SZ) return;
    int b = i / SZ, j = i % SZ;
    int op = g_top[b];
    float v;
    if (op < 64)       v = buffers[((size_t)b << 16) + ((size_t)op << 10) + j];
    else if (op < 128) v = g_hf[b][op - 64][j];
    else               v = 0.0f;
    out[i] = v;
}

// ---------------- launch ----------------
extern "C" void kernel_launch(void* const* d_in, const int* in_sizes, int n_in,
                              void* d_out, int out_size) {
    const float* buffers = (const float*)d_in[0];
    const int*   trans   = (const int*)d_in[1];
    const float* Wl      = (const float*)d_in[2];
    const float* Wr      = (const float*)d_in[3];
    const float* bl      = (const float*)d_in[4];
    float*       out     = (float*)d_out;

    int T  = in_sizes[1] / BSZ;
    int RL = (T + 1) / 2;
    if (RL > RMAX) RL = RMAX;

    static int attr_done = 0;
    if (!attr_done) {
        cudaFuncSetAttribute(spinn_kernel, cudaFuncAttributeMaxDynamicSharedMemorySize,
                             SMEM_TOTAL);
        cudaFuncSetAttribute(pr_kernel, cudaFuncAttributeMaxDynamicSharedMemorySize,
                             PR_SMEM);
        attr_done = 1;
    }

    schedule_kernel<<<8, 32>>>(trans, T);
    setup_kernel<<<8192 + 512, 256>>>(buffers);
    convert_w_kernel<<<2048, 256>>>(Wl, Wr, bl);

    dim3 prgrid(GN / 80, (BSZ * NLEAF) / 128);    // (32, 128)
    pr_kernel<<<prgrid, 256, PR_SMEM>>>();

    dim3 grid(GN / BN, BSZ / BM);                 // (32, 4) = 128 CTAs
    spinn_kernel<<<grid, NTH, SMEM_TOTAL>>>(buffers, RL);

    final_kernel<<<(BSZ * SZ + 255) / 256, 256>>>(buffers, out);
}